// round 3
// baseline (speedup 1.0000x reference)
#include <cuda_runtime.h>

// B=32, N=64, D=512
// score[b,i,j] = (dot(s_e[b,i,j,:], W) + bias) * adj[b,i,j], adj[b,0,1]=adj[b,1,0]=0
// Only i in {0,1} consumed. Outputs (float32, flattened tuple order):
//   final_id (32,2)=64 | s_e_score (32,2,64)=4096 | flag (32)=32

#define NB 32
#define NN 64
#define ND 512
#define GRID 128
#define TPB  512   // 16 warps

__device__ int g_done_counter = 0;   // stays 0 between launches (last block resets)

__global__ void __launch_bounds__(TPB, 1)
fused_kernel(const float* __restrict__ s_e,
             const float* __restrict__ adj,
             const float* __restrict__ W,
             const float* __restrict__ bias,
             float* __restrict__ out_id,
             float* __restrict__ out_score,
             float* __restrict__ out_flag) {
    int warp = threadIdx.x >> 5;
    int lane = threadIdx.x & 31;

    // ---- Phase 1: each warp computes 2 of the 4096 dot products ----
    const float4* wv = (const float4*)W;
    float4 w0 = wv[lane], w1 = wv[32 + lane], w2 = wv[64 + lane], w3 = wv[96 + lane];
    float bias0 = __ldg(bias);

    int gwarp = blockIdx.x * 16 + warp;      // 0..2047
#pragma unroll
    for (int r = 0; r < 2; ++r) {
        int p = gwarp * 2 + r;               // 0..4095
        int b = p >> 7;
        int i = (p >> 6) & 1;
        int j = p & 63;
        const float4* base =
            (const float4*)(s_e + ((size_t)((b * NN + i) * NN + j)) * ND);
        float4 a0 = base[lane];
        float4 a1 = base[32 + lane];
        float4 a2 = base[64 + lane];
        float4 a3 = base[96 + lane];

        float sum = a0.x * w0.x + a0.y * w0.y + a0.z * w0.z + a0.w * w0.w
                  + a1.x * w1.x + a1.y * w1.y + a1.z * w1.z + a1.w * w1.w
                  + a2.x * w2.x + a2.y * w2.y + a2.z * w2.z + a2.w * w2.w
                  + a3.x * w3.x + a3.y * w3.y + a3.z * w3.z + a3.w * w3.w;
#pragma unroll
        for (int off = 16; off; off >>= 1)
            sum += __shfl_xor_sync(0xffffffffu, sum, off);

        if (lane == 0) {
            float a = adj[(b * NN + i) * NN + j];
            if ((i == 0 && j == 1) || (i == 1 && j == 0)) a = 0.f;
            out_score[(b * 2 + i) * NN + j] = (sum + bias0) * a;
        }
    }

    // ---- Completion handshake: last block to finish runs the epilogue ----
    __syncthreads();
    __shared__ bool is_last;
    if (threadIdx.x == 0) {
        __threadfence();                               // scores visible chip-wide
        int prev = atomicAdd(&g_done_counter, 1);
        is_last = (prev == GRID - 1);
    }
    __syncthreads();
    if (!is_last) return;
    __threadfence();                                   // acquire

    // ---- Phase 2 (last block only): 64 argmaxes + flags, scores L2-hot ----
    __shared__ int s_ids[64];
    // 16 warps, 4 rows each (64 rows of 64 floats)
#pragma unroll
    for (int r = 0; r < 4; ++r) {
        int row = warp * 4 + r;                        // 0..63 == b*2 + i
        const float* rp = out_score + row * NN;
        float v0 = rp[lane];
        float v1 = rp[lane + 32];
        float v; int idx;
        if (v1 > v0) { v = v1; idx = lane + 32; }
        else         { v = v0; idx = lane; }
#pragma unroll
        for (int off = 16; off; off >>= 1) {
            float ov = __shfl_xor_sync(0xffffffffu, v, off);
            int   oi = __shfl_xor_sync(0xffffffffu, idx, off);
            if (ov > v || (ov == v && oi < idx)) { v = ov; idx = oi; }
        }
        if (lane == 0) {
            s_ids[row] = idx;
            out_id[row] = (float)idx;
        }
    }
    __syncthreads();

    if (threadIdx.x < NB) {
        int sub = s_ids[threadIdx.x * 2];
        int obj = s_ids[threadIdx.x * 2 + 1];
        float f = 0.f;
        if (sub > 0 && obj > 0)      f = 3.f;
        else if (sub > 0)            f = 1.f;
        else if (obj > 0)            f = 2.f;
        out_flag[threadIdx.x] = f;
    }

    if (threadIdx.x == 0) g_done_counter = 0;          // deterministic for replays
}

extern "C" void kernel_launch(void* const* d_in, const int* in_sizes, int n_in,
                              void* d_out, int out_size) {
    const float* s_e  = (const float*)d_in[0];
    const float* adj  = (const float*)d_in[1];
    const float* W    = (const float*)d_in[2];
    const float* bias = (const float*)d_in[3];

    float* out       = (float*)d_out;
    float* out_id    = out;             // 64
    float* out_score = out + 64;        // 4096
    float* out_flag  = out + 64 + 4096; // 32

    fused_kernel<<<GRID, TPB>>>(s_e, adj, W, bias, out_id, out_score, out_flag);
}